// round 14
// baseline (speedup 1.0000x reference)
#include <cuda_runtime.h>
#include <cuda_bf16.h>
#include <math.h>

// Problem constants
#define B_ 4
#define S_ 2048
#define E_ 1024
#define H_ 16
#define D_ 64
#define L_ 4
#define M_ 8192
#define ACT_ELEMS 8388608     // B*S*E
#define WELEMS 1048576        // E*E
#define GK E_

// ---------------------------------------------------------------------------
// Scratch (static device globals)
// ---------------------------------------------------------------------------
__device__ float g_o[ACT_ELEMS];
__device__ float g_x[ACT_ELEMS];
__device__ __nv_bfloat16 g_xb[ACT_ELEMS];      // plain bf16 activations
__device__ __nv_bfloat16 g_qb[ACT_ELEMS];      // pre-scaled by log2e/32
__device__ __nv_bfloat16 g_kb[ACT_ELEMS];      // masked rows zeroed
__device__ __nv_bfloat16 g_vb[ACT_ELEMS];
__device__ __nv_bfloat16 g_ab[ACT_ELEMS];      // attention out, plain bf16
__device__ __nv_bfloat16 g_wb[16 * WELEMS];    // all layers' Wq,Wk,Wv,Wo bf16

// ---------------------------------------------------------------------------
// PTX helpers
// ---------------------------------------------------------------------------
__device__ __forceinline__ void ldsm4(unsigned &r0, unsigned &r1, unsigned &r2,
                                      unsigned &r3, unsigned a) {
    asm volatile("ldmatrix.sync.aligned.m8n8.x4.shared.b16 {%0,%1,%2,%3}, [%4];"
                 : "=r"(r0), "=r"(r1), "=r"(r2), "=r"(r3) : "r"(a));
}
__device__ __forceinline__ void ldsm4t(unsigned &r0, unsigned &r1, unsigned &r2,
                                       unsigned &r3, unsigned a) {
    asm volatile("ldmatrix.sync.aligned.m8n8.x4.trans.shared.b16 {%0,%1,%2,%3}, [%4];"
                 : "=r"(r0), "=r"(r1), "=r"(r2), "=r"(r3) : "r"(a));
}
__device__ __forceinline__ void mma_bf16(float *c, const unsigned *a,
                                         unsigned b0, unsigned b1) {
    asm volatile(
        "mma.sync.aligned.m16n8k16.row.col.f32.bf16.bf16.f32 "
        "{%0,%1,%2,%3}, {%4,%5,%6,%7}, {%8,%9}, {%0,%1,%2,%3};"
        : "+f"(c[0]), "+f"(c[1]), "+f"(c[2]), "+f"(c[3])
        : "r"(a[0]), "r"(a[1]), "r"(a[2]), "r"(a[3]), "r"(b0), "r"(b1));
}
__device__ __forceinline__ void cpa16(unsigned s, const void *g) {
    asm volatile("cp.async.cg.shared.global [%0], [%1], 16;" :: "r"(s), "l"(g));
}
__device__ __forceinline__ void cpcommit() { asm volatile("cp.async.commit_group;"); }
__device__ __forceinline__ void cpwait0() { asm volatile("cp.async.wait_group 0;"); }

__device__ __forceinline__ unsigned pack2(float a, float b) {
    unsigned r;
    asm("cvt.rn.bf16x2.f32 %0, %1, %2;" : "=r"(r) : "f"(b), "f"(a));
    return r;
}
__device__ __forceinline__ float ex2f(float x) {
    float y;
    asm("ex2.approx.f32 %0, %1;" : "=f"(y) : "f"(x));
    return y;
}

// ---------------------------------------------------------------------------
// Conversion kernels
// ---------------------------------------------------------------------------
__global__ __launch_bounds__(256) void cvt_kernel(
    const float4 *__restrict__ src, uint2 *__restrict__ dst, int n4)
{
    int i = blockIdx.x * blockDim.x + threadIdx.x;
    if (i >= n4) return;
    float4 v = src[i];
    dst[i] = make_uint2(pack2(v.x, v.y), pack2(v.z, v.w));
}

// Weight prep, ALL layers in one launch: grid.y = weight, grid.z = layer.
__global__ __launch_bounds__(256) void wprep_kernel(
    const float4 *__restrict__ s0, const float4 *__restrict__ s1,
    const float4 *__restrict__ s2, const float4 *__restrict__ s3,
    uint2 *__restrict__ wb, int n4)
{
    int i = blockIdx.x * blockDim.x + threadIdx.x;
    if (i >= n4) return;
    int y = blockIdx.y, l = blockIdx.z;
    const float4 *src = ((y == 0) ? s0 : (y == 1) ? s1 : (y == 2) ? s2 : s3)
                        + (size_t)l * (WELEMS / 4) + i;
    float4 v = *src;
    wb[((size_t)l * 4 + y) * (WELEMS / 4) + i] =
        make_uint2(pack2(v.x, v.y), pack2(v.z, v.w));
}

// ---------------------------------------------------------------------------
// Plain bf16 GEMM: C = (A[M,K] @ W[N,K]^T + bias) * scale [* rowmask]
// Block 128x128, 4 warps, warp tile 64x64 (2x2 warp grid), k-chunk 64,
// 144B smem rows, cp.async 2-stage, 2 CTAs/SM.
// ---------------------------------------------------------------------------
#define PTILE2 18432            // 128 rows * 144 B
#define PSTAGE (2 * PTILE2)     // A + W = 36864
#define PGEMM_SMEM (2 * PSTAGE) // 73728

template <bool F32OUT>
__device__ __forceinline__ void pgemm_body(
    const __nv_bfloat16 *__restrict__ A, const __nv_bfloat16 *__restrict__ W,
    const float *__restrict__ bias, float scale, const int *__restrict__ kmask,
    __nv_bfloat16 *__restrict__ Cb, float *__restrict__ Cf)
{
    extern __shared__ char smc[];
    unsigned sb = (unsigned)__cvta_generic_to_shared(smc);

    const int tid = threadIdx.x;
    const int bm = blockIdx.y * 128, bn = blockIdx.x * 128;
    const int warp = tid >> 5, lane = tid & 31;
    const int wm = (warp >> 1) * 64, wn = (warp & 1) * 64;
    const int gid = lane >> 2, tig = lane & 3;
    const int lrow = lane & 15, lhalf = (lane >> 4) * 16;

    // Loader: each of 128 threads loads one A row and one W row per chunk.
    const __nv_bfloat16 *ga = A + (size_t)(bm + tid) * GK;
    const __nv_bfloat16 *gw = W + (size_t)(bn + tid) * GK;
    const unsigned sdA = sb + tid * 144;
    const unsigned sdW = sb + PTILE2 + tid * 144;

    float acc[4][8][4];
#pragma unroll
    for (int mt = 0; mt < 4; mt++)
#pragma unroll
        for (int nt = 0; nt < 8; nt++)
#pragma unroll
            for (int e = 0; e < 4; e++) acc[mt][nt][e] = 0.0f;

    // Prologue: chunk 0 into stage 0
#pragma unroll
    for (int c = 0; c < 8; c++) {
        cpa16(sdA + c * 16, ga + c * 8);
        cpa16(sdW + c * 16, gw + c * 8);
    }
    cpcommit();

    const int NK = GK / 64;           // 16
    for (int ks = 0; ks < NK; ks++) {
        cpwait0();
        __syncthreads();
        if (ks + 1 < NK) {
            unsigned st = ((ks + 1) & 1) * PSTAGE;
#pragma unroll
            for (int c = 0; c < 8; c++) {
                cpa16(sdA + st + c * 16, ga + (ks + 1) * 64 + c * 8);
                cpa16(sdW + st + c * 16, gw + (ks + 1) * 64 + c * 8);
            }
            cpcommit();
        }
        unsigned s0 = sb + (ks & 1) * PSTAGE;

#pragma unroll
        for (int k16 = 0; k16 < 4; k16++) {
            unsigned af[4][4], wf[8][2];
#pragma unroll
            for (int mt = 0; mt < 4; mt++) {
                unsigned addr = s0 + (wm + mt * 16 + lrow) * 144 + k16 * 32 + lhalf;
                ldsm4(af[mt][0], af[mt][1], af[mt][2], af[mt][3], addr);
            }
#pragma unroll
            for (int pr = 0; pr < 4; pr++) {
                unsigned addr = s0 + PTILE2 + (wn + pr * 16 + lrow) * 144 +
                                k16 * 32 + lhalf;
                unsigned r0, r1, r2, r3;
                ldsm4(r0, r1, r2, r3, addr);
                wf[2 * pr][0] = r0; wf[2 * pr + 1][0] = r1;
                wf[2 * pr][1] = r2; wf[2 * pr + 1][1] = r3;
            }
#pragma unroll
            for (int mt = 0; mt < 4; mt++)
#pragma unroll
                for (int nt = 0; nt < 8; nt++)
                    mma_bf16(acc[mt][nt], af[mt], wf[nt][0], wf[nt][1]);
        }
        __syncthreads();
    }

    // Per-row mask scales (K projection only): 0 for masked token rows.
    float rs[4][2];
#pragma unroll
    for (int mt = 0; mt < 4; mt++) {
        int r0 = bm + wm + mt * 16 + gid;
        if (kmask) {
            rs[mt][0] = kmask[r0] ? 0.0f : scale;
            rs[mt][1] = kmask[r0 + 8] ? 0.0f : scale;
        } else {
            rs[mt][0] = scale; rs[mt][1] = scale;
        }
    }

#pragma unroll
    for (int nt = 0; nt < 8; nt++) {
        int col = bn + wn + nt * 8 + 2 * tig;
        float2 bv2 = *(const float2 *)(bias + col);
#pragma unroll
        for (int mt = 0; mt < 4; mt++) {
            int r0 = bm + wm + mt * 16 + gid;
            float v00 = (acc[mt][nt][0] + bv2.x) * rs[mt][0];
            float v01 = (acc[mt][nt][1] + bv2.y) * rs[mt][0];
            float v10 = (acc[mt][nt][2] + bv2.x) * rs[mt][1];
            float v11 = (acc[mt][nt][3] + bv2.y) * rs[mt][1];
            if (F32OUT) {
                *(float2 *)(Cf + (size_t)r0 * E_ + col) = make_float2(v00, v01);
                *(float2 *)(Cf + (size_t)(r0 + 8) * E_ + col) = make_float2(v10, v11);
            } else {
                *(unsigned *)(Cb + (size_t)r0 * E_ + col) = pack2(v00, v01);
                *(unsigned *)(Cb + (size_t)(r0 + 8) * E_ + col) = pack2(v10, v11);
            }
        }
    }
}

// Fused QKV projection; Q pre-scaled by log2e/32, K rows zeroed by mask.
__global__ __launch_bounds__(128, 2) void gemm_qkv_plain(
    const __nv_bfloat16 *__restrict__ A, const __nv_bfloat16 *__restrict__ WB,
    const float *__restrict__ bq, const float *__restrict__ bk,
    const float *__restrict__ bv, const int *__restrict__ mask,
    __nv_bfloat16 *qb, __nv_bfloat16 *kb, __nv_bfloat16 *vb)
{
    const int z = blockIdx.z;
    const __nv_bfloat16 *W = WB + (size_t)z * WELEMS;
    const float *bias = (z == 0) ? bq : (z == 1) ? bk : bv;
    __nv_bfloat16 *C = (z == 0) ? qb : (z == 1) ? kb : vb;
    float scale = (z == 0) ? 0.04508422f : 1.0f;   // log2(e)/32
    const int *kmask = (z == 1) ? mask : nullptr;
    pgemm_body<false>(A, W, bias, scale, kmask, C, nullptr);
}

// Output projection (Wo), fp32 output for residual+LN.
__global__ __launch_bounds__(128, 2) void gemm_wo_plain(
    const __nv_bfloat16 *__restrict__ A, const __nv_bfloat16 *__restrict__ W,
    const float *__restrict__ bias, float *__restrict__ C)
{
    pgemm_body<true>(A, W, bias, 1.0f, nullptr, nullptr, C);
}

// ---------------------------------------------------------------------------
// Flash attention, plain bf16 mma, 4 warps x m32 q-rows (128 threads),
// 2 CTAs/SM. K/V ldsm shared across both m16 halves -> half the smem reads
// per MMA. No mask path (masked K rows are zero -> p = ex2(0) = 1 exactly).
// No online max. Q pre-scaled by log2e/32.
// ---------------------------------------------------------------------------
#define KT 9216                 // 64 rows x 144 B
#define AST (2 * KT)            // 18432 (K + V)
#define ATT_SMEM (2 * AST)      // 36864

__device__ __forceinline__ void attn_load_stage(
    unsigned sb, int st, int tid,
    const __nv_bfloat16 *K, const __nv_bfloat16 *V,
    size_t hb2, int kt)
{
    unsigned s0 = sb + st * AST;
    const int row = tid >> 1;            // 0..63
    const int half = tid & 1;            // which 64B half of the 128B row
    size_t gof = hb2 + (size_t)(kt * 64 + row) * E_ + half * 32;
    unsigned sr = s0 + row * 144 + half * 64;
#pragma unroll
    for (int j = 0; j < 4; j++) {
        cpa16(sr + j * 16,      K + gof + j * 8);
        cpa16(sr + KT + j * 16, V + gof + j * 8);
    }
}

__global__ __launch_bounds__(128, 2) void attn_mma_kernel(
    const __nv_bfloat16 *__restrict__ Q, const __nv_bfloat16 *__restrict__ K,
    const __nv_bfloat16 *__restrict__ V, __nv_bfloat16 *__restrict__ Ab)
{
    extern __shared__ char smc[];
    unsigned sb = (unsigned)__cvta_generic_to_shared(smc);

    const int qt = blockIdx.x, h = blockIdx.y, b = blockIdx.z;
    const int tid = threadIdx.x, warp = tid >> 5, lane = tid & 31;
    const int gid = lane >> 2, tig = lane & 3;
    const int lrow = lane & 15, lhalf = (lane >> 4) * 16;
    const size_t hb2 = (size_t)b * S_ * E_ + (size_t)h * D_;
    const int q0 = qt * 128 + warp * 32;

    // Q fragments for both m16 halves
    unsigned qf[2][4][4];
#pragma unroll
    for (int hh = 0; hh < 2; hh++) {
        const __nv_bfloat16 *r0 = Q + hb2 + (size_t)(q0 + hh * 16 + gid) * E_;
        const __nv_bfloat16 *r1 = r0 + 8 * E_;
#pragma unroll
        for (int kc = 0; kc < 4; kc++) {
            int c0 = kc * 16 + 2 * tig;
            qf[hh][kc][0] = *(const unsigned *)(r0 + c0);
            qf[hh][kc][1] = *(const unsigned *)(r1 + c0);
            qf[hh][kc][2] = *(const unsigned *)(r0 + c0 + 8);
            qf[hh][kc][3] = *(const unsigned *)(r1 + c0 + 8);
        }
    }

    float o[2][8][4];
#pragma unroll
    for (int hh = 0; hh < 2; hh++)
#pragma unroll
        for (int nt = 0; nt < 8; nt++)
#pragma unroll
            for (int e = 0; e < 4; e++) o[hh][nt][e] = 0.0f;
    float ls[2][2] = {{0.0f, 0.0f}, {0.0f, 0.0f}};

    attn_load_stage(sb, 0, tid, K, V, hb2, 0);
    cpcommit();

    const unsigned FULL = 0xffffffffu;

    for (int kt = 0; kt < 32; kt++) {
        cpwait0();
        __syncthreads();
        if (kt + 1 < 32) {
            attn_load_stage(sb, (kt + 1) & 1, tid, K, V, hb2, kt + 1);
            cpcommit();
        }
        unsigned s0 = sb + (kt & 1) * AST;

        // S = (Q*log2e/32) K^T for both halves, sharing the K ldsm
        float s[2][8][4];
#pragma unroll
        for (int hh = 0; hh < 2; hh++)
#pragma unroll
            for (int nt = 0; nt < 8; nt++)
                s[hh][nt][0] = s[hh][nt][1] = s[hh][nt][2] = s[hh][nt][3] = 0.0f;

#pragma unroll
        for (int nt16 = 0; nt16 < 4; nt16++) {
#pragma unroll
            for (int kc = 0; kc < 4; kc++) {
                unsigned addr = s0 + (nt16 * 16 + lrow) * 144 + kc * 32 + lhalf;
                unsigned k0, k1, k2, k3;
                ldsm4(k0, k1, k2, k3, addr);
                mma_bf16(s[0][2 * nt16],     qf[0][kc], k0, k2);
                mma_bf16(s[0][2 * nt16 + 1], qf[0][kc], k1, k3);
                mma_bf16(s[1][2 * nt16],     qf[1][kc], k0, k2);
                mma_bf16(s[1][2 * nt16 + 1], qf[1][kc], k1, k3);
            }
        }

        // p = exp2(s), accumulate denominators, pack into PV A-fragments
        unsigned pb[2][4][4];
#pragma unroll
        for (int hh = 0; hh < 2; hh++) {
#pragma unroll
            for (int nt = 0; nt < 8; nt++) {
                s[hh][nt][0] = ex2f(s[hh][nt][0]);
                s[hh][nt][1] = ex2f(s[hh][nt][1]);
                s[hh][nt][2] = ex2f(s[hh][nt][2]);
                s[hh][nt][3] = ex2f(s[hh][nt][3]);
                ls[hh][0] += s[hh][nt][0] + s[hh][nt][1];
                ls[hh][1] += s[hh][nt][2] + s[hh][nt][3];
            }
#pragma unroll
            for (int kc = 0; kc < 4; kc++) {
                pb[hh][kc][0] = pack2(s[hh][2 * kc][0],     s[hh][2 * kc][1]);
                pb[hh][kc][1] = pack2(s[hh][2 * kc][2],     s[hh][2 * kc][3]);
                pb[hh][kc][2] = pack2(s[hh][2 * kc + 1][0], s[hh][2 * kc + 1][1]);
                pb[hh][kc][3] = pack2(s[hh][2 * kc + 1][2], s[hh][2 * kc + 1][3]);
            }
        }

        // O += P V for both halves, sharing the V ldsm
        const int vm = lane >> 3, vi = lane & 7;
#pragma unroll
        for (int kc = 0; kc < 4; kc++) {
#pragma unroll
            for (int j = 0; j < 4; j++) {
                unsigned vaddr = s0 + KT +
                                 (kc * 16 + ((vm >> 1) & 1) * 8 + vi) * 144 +
                                 (j * 16 + (vm & 1) * 8) * 2;
                unsigned v0, v1, v2, v3;
                ldsm4t(v0, v1, v2, v3, vaddr);
                mma_bf16(o[0][2 * j],     pb[0][kc], v0, v2);
                mma_bf16(o[0][2 * j + 1], pb[0][kc], v1, v3);
                mma_bf16(o[1][2 * j],     pb[1][kc], v0, v2);
                mma_bf16(o[1][2 * j + 1], pb[1][kc], v1, v3);
            }
        }
        __syncthreads();
    }

    // quad-reduce denominators, normalize + write bf16, both halves
#pragma unroll
    for (int hh = 0; hh < 2; hh++) {
        ls[hh][0] += __shfl_xor_sync(FULL, ls[hh][0], 1);
        ls[hh][0] += __shfl_xor_sync(FULL, ls[hh][0], 2);
        ls[hh][1] += __shfl_xor_sync(FULL, ls[hh][1], 1);
        ls[hh][1] += __shfl_xor_sync(FULL, ls[hh][1], 2);
        float i0 = 1.0f / ls[hh][0], i1 = 1.0f / ls[hh][1];
#pragma unroll
        for (int nt = 0; nt < 8; nt++) {
            int col = nt * 8 + 2 * tig;
            size_t ia = hb2 + (size_t)(q0 + hh * 16 + gid) * E_ + col;
            size_t ib = hb2 + (size_t)(q0 + hh * 16 + gid + 8) * E_ + col;
            *(unsigned *)(Ab + ia) = pack2(o[hh][nt][0] * i0, o[hh][nt][1] * i0);
            *(unsigned *)(Ab + ib) = pack2(o[hh][nt][2] * i1, o[hh][nt][3] * i1);
        }
    }
}

// ---------------------------------------------------------------------------
// Residual add + LayerNorm; emits fp32 out + plain bf16 for next QKV input.
// ---------------------------------------------------------------------------
__global__ __launch_bounds__(256) void resid_ln_kernel(
    const float *__restrict__ o, const float *__restrict__ x,
    const float *__restrict__ gamma, const float *__restrict__ beta,
    float *__restrict__ out, __nv_bfloat16 *__restrict__ ob)
{
    const int row = blockIdx.x;
    const int tid = threadIdx.x;
    const float *orow = o + (size_t)row * E_;
    const float *xrow = x + (size_t)row * E_;

    float y[4];
    float s = 0.0f, s2 = 0.0f;
#pragma unroll
    for (int t = 0; t < 4; t++) {
        int c = tid + t * 256;
        y[t] = orow[c] + xrow[c];
        s += y[t];
        s2 += y[t] * y[t];
    }

    __shared__ float red[16];
#pragma unroll
    for (int off = 16; off > 0; off >>= 1) {
        s += __shfl_xor_sync(0xffffffffu, s, off);
        s2 += __shfl_xor_sync(0xffffffffu, s2, off);
    }
    const int warp = tid >> 5, lane = tid & 31;
    if (lane == 0) { red[warp] = s; red[8 + warp] = s2; }
    __syncthreads();

    float ts = 0.0f, ts2 = 0.0f;
#pragma unroll
    for (int w = 0; w < 8; w++) { ts += red[w]; ts2 += red[8 + w]; }

    const float mu = ts * (1.0f / E_);
    const float var = ts2 * (1.0f / E_) - mu * mu;
    const float inv = rsqrtf(var + 1e-5f);

    float *outrow = out + (size_t)row * E_;
#pragma unroll
    for (int t = 0; t < 4; t++) {
        int c = tid + t * 256;
        float val = (y[t] - mu) * inv * gamma[c] + beta[c];
        outrow[c] = val;
        ob[(size_t)row * E_ + c] = __float2bfloat16(val);
    }
}

// ---------------------------------------------------------------------------
// Launch
// ---------------------------------------------------------------------------
extern "C" void kernel_launch(void *const *d_in, const int *in_sizes, int n_in,
                              void *d_out, int out_size)
{
    (void)in_sizes; (void)n_in; (void)out_size;

    const float *value = (const float *)d_in[0];
    const int *mask = (const int *)d_in[1];
    const float *Wq = (const float *)d_in[2];  const float *bq = (const float *)d_in[3];
    const float *Wk = (const float *)d_in[4];  const float *bk = (const float *)d_in[5];
    const float *Wv = (const float *)d_in[6];  const float *bv = (const float *)d_in[7];
    const float *Wo = (const float *)d_in[8];  const float *bo = (const float *)d_in[9];
    const float *gamma = (const float *)d_in[10];
    const float *beta = (const float *)d_in[11];
    float *out = (float *)d_out;

    float *o, *x;
    __nv_bfloat16 *xb, *qb, *kb, *vb, *ab, *wb;
    cudaGetSymbolAddress((void **)&o, g_o);
    cudaGetSymbolAddress((void **)&x, g_x);
    cudaGetSymbolAddress((void **)&xb, g_xb);
    cudaGetSymbolAddress((void **)&qb, g_qb);
    cudaGetSymbolAddress((void **)&kb, g_kb);
    cudaGetSymbolAddress((void **)&vb, g_vb);
    cudaGetSymbolAddress((void **)&ab, g_ab);
    cudaGetSymbolAddress((void **)&wb, g_wb);

    cudaFuncSetAttribute(gemm_qkv_plain,
                         cudaFuncAttributeMaxDynamicSharedMemorySize, PGEMM_SMEM);
    cudaFuncSetAttribute(gemm_wo_plain,
                         cudaFuncAttributeMaxDynamicSharedMemorySize, PGEMM_SMEM);
    cudaFuncSetAttribute(attn_mma_kernel,
                         cudaFuncAttributeMaxDynamicSharedMemorySize, ATT_SMEM);

    dim3 qkvgrid(E_ / 128, M_ / 128, 3);
    dim3 ogrid(E_ / 128, M_ / 128, 1);
    dim3 agrid(S_ / 128, H_, B_);
    dim3 wgrid(WELEMS / 4 / 256, 4, L_);
    const int n4a = ACT_ELEMS / 4;

    cvt_kernel<<<(n4a + 255) / 256, 256>>>((const float4 *)value,
                                           (uint2 *)xb, n4a);
    // All layers' weights converted once, up front.
    wprep_kernel<<<wgrid, 256>>>(
        (const float4 *)Wq, (const float4 *)Wk,
        (const float4 *)Wv, (const float4 *)Wo,
        (uint2 *)wb, WELEMS / 4);

    const float *xin = value;
    for (int l = 0; l < L_; l++) {
        size_t bof = (size_t)l * E_;
        __nv_bfloat16 *wl = wb + (size_t)l * 4 * WELEMS;

        gemm_qkv_plain<<<qkvgrid, 128, PGEMM_SMEM>>>(
            xb, wl, bq + bof, bk + bof, bv + bof, mask, qb, kb, vb);

        attn_mma_kernel<<<agrid, 128, ATT_SMEM>>>(qb, kb, vb, ab);

        gemm_wo_plain<<<ogrid, 128, PGEMM_SMEM>>>(
            ab, wl + 3 * WELEMS, bo + bof, o);

        float *dst = (l == L_ - 1) ? out : x;
        resid_ln_kernel<<<M_, 256>>>(o, xin, gamma + bof, beta + bof, dst, xb);
        xin = x;
    }
}

// round 15
// speedup vs baseline: 1.0571x; 1.0571x over previous
#include <cuda_runtime.h>
#include <cuda_bf16.h>
#include <math.h>

// Problem constants
#define B_ 4
#define S_ 2048
#define E_ 1024
#define H_ 16
#define D_ 64
#define L_ 4
#define M_ 8192
#define ACT_ELEMS 8388608     // B*S*E
#define WELEMS 1048576        // E*E
#define GK E_

// ---------------------------------------------------------------------------
// Scratch (static device globals)
// ---------------------------------------------------------------------------
__device__ float g_o[ACT_ELEMS];
__device__ float g_x[ACT_ELEMS];
__device__ __nv_bfloat16 g_xb[ACT_ELEMS];      // plain bf16 activations
__device__ __nv_bfloat16 g_qb[ACT_ELEMS];      // pre-scaled by log2e/32
__device__ __nv_bfloat16 g_kb[ACT_ELEMS];      // masked rows zeroed
__device__ __nv_bfloat16 g_vb[ACT_ELEMS];
__device__ __nv_bfloat16 g_ab[ACT_ELEMS];      // attention out, plain bf16
__device__ __nv_bfloat16 g_wb[16 * WELEMS];    // all layers' Wq,Wk,Wv,Wo bf16

// ---------------------------------------------------------------------------
// PTX helpers
// ---------------------------------------------------------------------------
__device__ __forceinline__ void ldsm4(unsigned &r0, unsigned &r1, unsigned &r2,
                                      unsigned &r3, unsigned a) {
    asm volatile("ldmatrix.sync.aligned.m8n8.x4.shared.b16 {%0,%1,%2,%3}, [%4];"
                 : "=r"(r0), "=r"(r1), "=r"(r2), "=r"(r3) : "r"(a));
}
__device__ __forceinline__ void ldsm4t(unsigned &r0, unsigned &r1, unsigned &r2,
                                       unsigned &r3, unsigned a) {
    asm volatile("ldmatrix.sync.aligned.m8n8.x4.trans.shared.b16 {%0,%1,%2,%3}, [%4];"
                 : "=r"(r0), "=r"(r1), "=r"(r2), "=r"(r3) : "r"(a));
}
__device__ __forceinline__ void mma_bf16(float *c, const unsigned *a,
                                         unsigned b0, unsigned b1) {
    asm volatile(
        "mma.sync.aligned.m16n8k16.row.col.f32.bf16.bf16.f32 "
        "{%0,%1,%2,%3}, {%4,%5,%6,%7}, {%8,%9}, {%0,%1,%2,%3};"
        : "+f"(c[0]), "+f"(c[1]), "+f"(c[2]), "+f"(c[3])
        : "r"(a[0]), "r"(a[1]), "r"(a[2]), "r"(a[3]), "r"(b0), "r"(b1));
}
__device__ __forceinline__ void cpa16(unsigned s, const void *g) {
    asm volatile("cp.async.cg.shared.global [%0], [%1], 16;" :: "r"(s), "l"(g));
}
__device__ __forceinline__ void cpcommit() { asm volatile("cp.async.commit_group;"); }
__device__ __forceinline__ void cpwait0() { asm volatile("cp.async.wait_group 0;"); }

__device__ __forceinline__ unsigned pack2(float a, float b) {
    unsigned r;
    asm("cvt.rn.bf16x2.f32 %0, %1, %2;" : "=r"(r) : "f"(b), "f"(a));
    return r;
}
__device__ __forceinline__ float ex2f(float x) {
    float y;
    asm("ex2.approx.f32 %0, %1;" : "=f"(y) : "f"(x));
    return y;
}

// ---------------------------------------------------------------------------
// Conversion kernels
// ---------------------------------------------------------------------------
__global__ __launch_bounds__(256) void cvt_kernel(
    const float4 *__restrict__ src, uint2 *__restrict__ dst, int n4)
{
    int i = blockIdx.x * blockDim.x + threadIdx.x;
    if (i >= n4) return;
    float4 v = src[i];
    dst[i] = make_uint2(pack2(v.x, v.y), pack2(v.z, v.w));
}

// Weight prep, ALL layers in one launch: grid.y = weight, grid.z = layer.
__global__ __launch_bounds__(256) void wprep_kernel(
    const float4 *__restrict__ s0, const float4 *__restrict__ s1,
    const float4 *__restrict__ s2, const float4 *__restrict__ s3,
    uint2 *__restrict__ wb, int n4)
{
    int i = blockIdx.x * blockDim.x + threadIdx.x;
    if (i >= n4) return;
    int y = blockIdx.y, l = blockIdx.z;
    const float4 *src = ((y == 0) ? s0 : (y == 1) ? s1 : (y == 2) ? s2 : s3)
                        + (size_t)l * (WELEMS / 4) + i;
    float4 v = *src;
    wb[((size_t)l * 4 + y) * (WELEMS / 4) + i] =
        make_uint2(pack2(v.x, v.y), pack2(v.z, v.w));
}

// ---------------------------------------------------------------------------
// Plain bf16 GEMM: C = (A[M,K] @ W[N,K]^T + bias) * scale [* rowmask]
// Block 256x128, 8 warps, warp tile 64x64 (4x2 warp grid), k-chunk 64,
// 144B smem rows, cp.async 2-stage, 1 CTA/SM (108KB smem).
// Doubled arithmetic intensity vs 128x128: 48KB loaded per 4.2MF chunk.
// ---------------------------------------------------------------------------
#define ATILE 36864             // 256 rows * 144 B (A)
#define WTILE 18432             // 128 rows * 144 B (W)
#define PSTAGE (ATILE + WTILE)  // 55296
#define PGEMM_SMEM (2 * PSTAGE) // 110592

template <bool F32OUT>
__device__ __forceinline__ void pgemm_body(
    const __nv_bfloat16 *__restrict__ A, const __nv_bfloat16 *__restrict__ W,
    const float *__restrict__ bias, float scale, const int *__restrict__ kmask,
    __nv_bfloat16 *__restrict__ Cb, float *__restrict__ Cf)
{
    extern __shared__ char smc[];
    unsigned sb = (unsigned)__cvta_generic_to_shared(smc);

    const int tid = threadIdx.x;
    const int bm = blockIdx.y * 256, bn = blockIdx.x * 128;
    const int warp = tid >> 5, lane = tid & 31;
    const int wm = (warp >> 1) * 64, wn = (warp & 1) * 64;
    const int gid = lane >> 2, tig = lane & 3;
    const int lrow = lane & 15, lhalf = (lane >> 4) * 16;

    // Loaders: every thread loads its A row; threads 0-127 also load a W row.
    const __nv_bfloat16 *ga = A + (size_t)(bm + tid) * GK;
    const __nv_bfloat16 *gw = W + (size_t)(bn + (tid & 127)) * GK;
    const unsigned sdA = sb + tid * 144;
    const unsigned sdW = sb + ATILE + (tid & 127) * 144;
    const bool loadw = tid < 128;

    float acc[4][8][4];
#pragma unroll
    for (int mt = 0; mt < 4; mt++)
#pragma unroll
        for (int nt = 0; nt < 8; nt++)
#pragma unroll
            for (int e = 0; e < 4; e++) acc[mt][nt][e] = 0.0f;

    // Prologue: chunk 0 into stage 0
#pragma unroll
    for (int c = 0; c < 8; c++) {
        cpa16(sdA + c * 16, ga + c * 8);
        if (loadw) cpa16(sdW + c * 16, gw + c * 8);
    }
    cpcommit();

    const int NK = GK / 64;           // 16
    for (int ks = 0; ks < NK; ks++) {
        cpwait0();
        __syncthreads();
        if (ks + 1 < NK) {
            unsigned st = ((ks + 1) & 1) * PSTAGE;
#pragma unroll
            for (int c = 0; c < 8; c++) {
                cpa16(sdA + st + c * 16, ga + (ks + 1) * 64 + c * 8);
                if (loadw) cpa16(sdW + st + c * 16, gw + (ks + 1) * 64 + c * 8);
            }
            cpcommit();
        }
        unsigned s0 = sb + (ks & 1) * PSTAGE;

#pragma unroll
        for (int k16 = 0; k16 < 4; k16++) {
            unsigned af[4][4], wf[8][2];
#pragma unroll
            for (int mt = 0; mt < 4; mt++) {
                unsigned addr = s0 + (wm + mt * 16 + lrow) * 144 + k16 * 32 + lhalf;
                ldsm4(af[mt][0], af[mt][1], af[mt][2], af[mt][3], addr);
            }
#pragma unroll
            for (int pr = 0; pr < 4; pr++) {
                unsigned addr = s0 + ATILE + (wn + pr * 16 + lrow) * 144 +
                                k16 * 32 + lhalf;
                unsigned r0, r1, r2, r3;
                ldsm4(r0, r1, r2, r3, addr);
                wf[2 * pr][0] = r0; wf[2 * pr + 1][0] = r1;
                wf[2 * pr][1] = r2; wf[2 * pr + 1][1] = r3;
            }
#pragma unroll
            for (int mt = 0; mt < 4; mt++)
#pragma unroll
                for (int nt = 0; nt < 8; nt++)
                    mma_bf16(acc[mt][nt], af[mt], wf[nt][0], wf[nt][1]);
        }
        __syncthreads();
    }

    // Per-row mask scales (K projection only): 0 for masked token rows.
    float rs[4][2];
#pragma unroll
    for (int mt = 0; mt < 4; mt++) {
        int r0 = bm + wm + mt * 16 + gid;
        if (kmask) {
            rs[mt][0] = kmask[r0] ? 0.0f : scale;
            rs[mt][1] = kmask[r0 + 8] ? 0.0f : scale;
        } else {
            rs[mt][0] = scale; rs[mt][1] = scale;
        }
    }

#pragma unroll
    for (int nt = 0; nt < 8; nt++) {
        int col = bn + wn + nt * 8 + 2 * tig;
        float2 bv2 = *(const float2 *)(bias + col);
#pragma unroll
        for (int mt = 0; mt < 4; mt++) {
            int r0 = bm + wm + mt * 16 + gid;
            float v00 = (acc[mt][nt][0] + bv2.x) * rs[mt][0];
            float v01 = (acc[mt][nt][1] + bv2.y) * rs[mt][0];
            float v10 = (acc[mt][nt][2] + bv2.x) * rs[mt][1];
            float v11 = (acc[mt][nt][3] + bv2.y) * rs[mt][1];
            if (F32OUT) {
                *(float2 *)(Cf + (size_t)r0 * E_ + col) = make_float2(v00, v01);
                *(float2 *)(Cf + (size_t)(r0 + 8) * E_ + col) = make_float2(v10, v11);
            } else {
                *(unsigned *)(Cb + (size_t)r0 * E_ + col) = pack2(v00, v01);
                *(unsigned *)(Cb + (size_t)(r0 + 8) * E_ + col) = pack2(v10, v11);
            }
        }
    }
}

// Fused QKV projection; Q pre-scaled by log2e/32, K rows zeroed by mask.
__global__ __launch_bounds__(256, 1) void gemm_qkv_plain(
    const __nv_bfloat16 *__restrict__ A, const __nv_bfloat16 *__restrict__ WB,
    const float *__restrict__ bq, const float *__restrict__ bk,
    const float *__restrict__ bv, const int *__restrict__ mask,
    __nv_bfloat16 *qb, __nv_bfloat16 *kb, __nv_bfloat16 *vb)
{
    const int z = blockIdx.z;
    const __nv_bfloat16 *W = WB + (size_t)z * WELEMS;
    const float *bias = (z == 0) ? bq : (z == 1) ? bk : bv;
    __nv_bfloat16 *C = (z == 0) ? qb : (z == 1) ? kb : vb;
    float scale = (z == 0) ? 0.04508422f : 1.0f;   // log2(e)/32
    const int *kmask = (z == 1) ? mask : nullptr;
    pgemm_body<false>(A, W, bias, scale, kmask, C, nullptr);
}

// Output projection (Wo), fp32 output for residual+LN.
__global__ __launch_bounds__(256, 1) void gemm_wo_plain(
    const __nv_bfloat16 *__restrict__ A, const __nv_bfloat16 *__restrict__ W,
    const float *__restrict__ bias, float *__restrict__ C)
{
    pgemm_body<true>(A, W, bias, 1.0f, nullptr, nullptr, C);
}

// ---------------------------------------------------------------------------
// Flash attention (Round-13 config: 8 warps x m16, 256 thr, 2 CTAs/SM).
// No mask path (masked K rows are zero -> p = ex2(0) = 1 exactly).
// No online max. Q pre-scaled by log2e/32. 2-stage cp.async pipeline.
// ---------------------------------------------------------------------------
#define KT 9216                 // 64 rows x 144 B
#define AST (2 * KT)            // 18432 (K + V)
#define ATT_SMEM (2 * AST)      // 36864

__device__ __forceinline__ void attn_load_stage(
    unsigned sb, int st, int tid,
    const __nv_bfloat16 *K, const __nv_bfloat16 *V,
    size_t hb2, int kt)
{
    unsigned s0 = sb + st * AST;
    const int row = tid >> 2;
    const int cb = (tid & 3) * 2;
    size_t gof = hb2 + (size_t)(kt * 64 + row) * E_ + cb * 8;
    unsigned sr = s0 + row * 144 + cb * 16;
    cpa16(sr,           K + gof);
    cpa16(sr + 16,      K + gof + 8);
    cpa16(sr + KT,      V + gof);
    cpa16(sr + KT + 16, V + gof + 8);
}

__global__ __launch_bounds__(256, 2) void attn_mma_kernel(
    const __nv_bfloat16 *__restrict__ Q, const __nv_bfloat16 *__restrict__ K,
    const __nv_bfloat16 *__restrict__ V, __nv_bfloat16 *__restrict__ Ab)
{
    extern __shared__ char smc[];
    unsigned sb = (unsigned)__cvta_generic_to_shared(smc);

    const int qt = blockIdx.x, h = blockIdx.y, b = blockIdx.z;
    const int tid = threadIdx.x, warp = tid >> 5, lane = tid & 31;
    const int gid = lane >> 2, tig = lane & 3;
    const int lrow = lane & 15, lhalf = (lane >> 4) * 16;
    const size_t hb2 = (size_t)b * S_ * E_ + (size_t)h * D_;
    const int q0 = qt * 128 + warp * 16;

    unsigned qf[4][4];
    {
        const __nv_bfloat16 *r0 = Q + hb2 + (size_t)(q0 + gid) * E_;
        const __nv_bfloat16 *r1 = r0 + 8 * E_;
#pragma unroll
        for (int kc = 0; kc < 4; kc++) {
            int c0 = kc * 16 + 2 * tig;
            qf[kc][0] = *(const unsigned *)(r0 + c0);
            qf[kc][1] = *(const unsigned *)(r1 + c0);
            qf[kc][2] = *(const unsigned *)(r0 + c0 + 8);
            qf[kc][3] = *(const unsigned *)(r1 + c0 + 8);
        }
    }

    float o[8][4];
#pragma unroll
    for (int nt = 0; nt < 8; nt++)
#pragma unroll
        for (int e = 0; e < 4; e++) o[nt][e] = 0.0f;
    float lsum0 = 0.0f, lsum1 = 0.0f;

    attn_load_stage(sb, 0, tid, K, V, hb2, 0);
    cpcommit();

    const unsigned FULL = 0xffffffffu;

    for (int kt = 0; kt < 32; kt++) {
        cpwait0();
        __syncthreads();
        if (kt + 1 < 32) {
            attn_load_stage(sb, (kt + 1) & 1, tid, K, V, hb2, kt + 1);
            cpcommit();
        }
        unsigned s0 = sb + (kt & 1) * AST;

        // S = (Q*log2e/32) K^T  == energy in log2 domain (0 for masked keys)
        float s[8][4];
#pragma unroll
        for (int nt = 0; nt < 8; nt++)
            s[nt][0] = s[nt][1] = s[nt][2] = s[nt][3] = 0.0f;

#pragma unroll
        for (int nt16 = 0; nt16 < 4; nt16++) {
#pragma unroll
            for (int kc = 0; kc < 4; kc++) {
                unsigned addr = s0 + (nt16 * 16 + lrow) * 144 + kc * 32 + lhalf;
                unsigned k0, k1, k2, k3;
                ldsm4(k0, k1, k2, k3, addr);
                mma_bf16(s[2 * nt16],     qf[kc], k0, k2);
                mma_bf16(s[2 * nt16 + 1], qf[kc], k1, k3);
            }
        }

        // p = exp2(s), accumulate denominator (masked keys give p = 1)
#pragma unroll
        for (int nt = 0; nt < 8; nt++) {
            s[nt][0] = ex2f(s[nt][0]);
            s[nt][1] = ex2f(s[nt][1]);
            s[nt][2] = ex2f(s[nt][2]);
            s[nt][3] = ex2f(s[nt][3]);
            lsum0 += s[nt][0] + s[nt][1];
            lsum1 += s[nt][2] + s[nt][3];
        }

        // O += P V  (P C-layout packs directly into PV A-fragment)
        const int vm = lane >> 3, vi = lane & 7;
#pragma unroll
        for (int kc = 0; kc < 4; kc++) {
            unsigned pb[4];
            pb[0] = pack2(s[2 * kc][0],     s[2 * kc][1]);
            pb[1] = pack2(s[2 * kc][2],     s[2 * kc][3]);
            pb[2] = pack2(s[2 * kc + 1][0], s[2 * kc + 1][1]);
            pb[3] = pack2(s[2 * kc + 1][2], s[2 * kc + 1][3]);
#pragma unroll
            for (int j = 0; j < 4; j++) {
                unsigned vaddr = s0 + KT +
                                 (kc * 16 + ((vm >> 1) & 1) * 8 + vi) * 144 +
                                 (j * 16 + (vm & 1) * 8) * 2;
                unsigned v0, v1, v2, v3;
                ldsm4t(v0, v1, v2, v3, vaddr);
                mma_bf16(o[2 * j],     pb, v0, v2);
                mma_bf16(o[2 * j + 1], pb, v1, v3);
            }
        }
        __syncthreads();
    }

    // one quad-reduction of the denominators, then normalize + write bf16
    lsum0 += __shfl_xor_sync(FULL, lsum0, 1);
    lsum0 += __shfl_xor_sync(FULL, lsum0, 2);
    lsum1 += __shfl_xor_sync(FULL, lsum1, 1);
    lsum1 += __shfl_xor_sync(FULL, lsum1, 2);
    float i0 = 1.0f / lsum0, i1 = 1.0f / lsum1;
#pragma unroll
    for (int nt = 0; nt < 8; nt++) {
        int col = nt * 8 + 2 * tig;
        size_t ia = hb2 + (size_t)(q0 + gid) * E_ + col;
        size_t ib = hb2 + (size_t)(q0 + gid + 8) * E_ + col;
        *(unsigned *)(Ab + ia) = pack2(o[nt][0] * i0, o[nt][1] * i0);
        *(unsigned *)(Ab + ib) = pack2(o[nt][2] * i1, o[nt][3] * i1);
    }
}

// ---------------------------------------------------------------------------
// Residual add + LayerNorm; emits fp32 out + plain bf16 for next QKV input.
// ---------------------------------------------------------------------------
__global__ __launch_bounds__(256) void resid_ln_kernel(
    const float *__restrict__ o, const float *__restrict__ x,
    const float *__restrict__ gamma, const float *__restrict__ beta,
    float *__restrict__ out, __nv_bfloat16 *__restrict__ ob)
{
    const int row = blockIdx.x;
    const int tid = threadIdx.x;
    const float *orow = o + (size_t)row * E_;
    const float *xrow = x + (size_t)row * E_;

    float y[4];
    float s = 0.0f, s2 = 0.0f;
#pragma unroll
    for (int t = 0; t < 4; t++) {
        int c = tid + t * 256;
        y[t] = orow[c] + xrow[c];
        s += y[t];
        s2 += y[t] * y[t];
    }

    __shared__ float red[16];
#pragma unroll
    for (int off = 16; off > 0; off >>= 1) {
        s += __shfl_xor_sync(0xffffffffu, s, off);
        s2 += __shfl_xor_sync(0xffffffffu, s2, off);
    }
    const int warp = tid >> 5, lane = tid & 31;
    if (lane == 0) { red[warp] = s; red[8 + warp] = s2; }
    __syncthreads();

    float ts = 0.0f, ts2 = 0.0f;
#pragma unroll
    for (int w = 0; w < 8; w++) { ts += red[w]; ts2 += red[8 + w]; }

    const float mu = ts * (1.0f / E_);
    const float var = ts2 * (1.0f / E_) - mu * mu;
    const float inv = rsqrtf(var + 1e-5f);

    float *outrow = out + (size_t)row * E_;
#pragma unroll
    for (int t = 0; t < 4; t++) {
        int c = tid + t * 256;
        float val = (y[t] - mu) * inv * gamma[c] + beta[c];
        outrow[c] = val;
        ob[(size_t)row * E_ + c] = __float2bfloat16(val);
    }
}

// ---------------------------------------------------------------------------
// Launch
// ---------------------------------------------------------------------------
extern "C" void kernel_launch(void *const *d_in, const int *in_sizes, int n_in,
                              void *d_out, int out_size)
{
    (void)in_sizes; (void)n_in; (void)out_size;

    const float *value = (const float *)d_in[0];
    const int *mask = (const int *)d_in[1];
    const float *Wq = (const float *)d_in[2];  const float *bq = (const float *)d_in[3];
    const float *Wk = (const float *)d_in[4];  const float *bk = (const float *)d_in[5];
    const float *Wv = (const float *)d_in[6];  const float *bv = (const float *)d_in[7];
    const float *Wo = (const float *)d_in[8];  const float *bo = (const float *)d_in[9];
    const float *gamma = (const float *)d_in[10];
    const float *beta = (const float *)d_in[11];
    float *out = (float *)d_out;

    float *o, *x;
    __nv_bfloat16 *xb, *qb, *kb, *vb, *ab, *wb;
    cudaGetSymbolAddress((void **)&o, g_o);
    cudaGetSymbolAddress((void **)&x, g_x);
    cudaGetSymbolAddress((void **)&xb, g_xb);
    cudaGetSymbolAddress((void **)&qb, g_qb);
    cudaGetSymbolAddress((void **)&kb, g_kb);
    cudaGetSymbolAddress((void **)&vb, g_vb);
    cudaGetSymbolAddress((void **)&ab, g_ab);
    cudaGetSymbolAddress((void **)&wb, g_wb);

    cudaFuncSetAttribute(gemm_qkv_plain,
                         cudaFuncAttributeMaxDynamicSharedMemorySize, PGEMM_SMEM);
    cudaFuncSetAttribute(gemm_wo_plain,
                         cudaFuncAttributeMaxDynamicSharedMemorySize, PGEMM_SMEM);
    cudaFuncSetAttribute(attn_mma_kernel,
                         cudaFuncAttributeMaxDynamicSharedMemorySize, ATT_SMEM);

    dim3 qkvgrid(E_ / 128, M_ / 256, 3);   // (8, 32, 3)
    dim3 ogrid(E_ / 128, M_ / 256, 1);     // (8, 32)
    dim3 agrid(S_ / 128, H_, B_);
    dim3 wgrid(WELEMS / 4 / 256, 4, L_);
    const int n4a = ACT_ELEMS / 4;

    cvt_kernel<<<(n4a + 255) / 256, 256>>>((const float4 *)value,
                                           (uint2 *)xb, n4a);
    // All layers' weights converted once, up front.
    wprep_kernel<<<wgrid, 256>>>(
        (const float4 *)Wq, (const float4 *)Wk,
        (const float4 *)Wv, (const float4 *)Wo,
        (uint2 *)wb, WELEMS / 4);

    const float *xin = value;
    for (int l = 0; l < L_; l++) {
        size_t bof = (size_t)l * E_;
        __nv_bfloat16 *wl = wb + (size_t)l * 4 * WELEMS;

        gemm_qkv_plain<<<qkvgrid, 256, PGEMM_SMEM>>>(
            xb, wl, bq + bof, bk + bof, bv + bof, mask, qb, kb, vb);

        attn_mma_kernel<<<agrid, 256, ATT_SMEM>>>(qb, kb, vb, ab);

        gemm_wo_plain<<<ogrid, 256, PGEMM_SMEM>>>(
            ab, wl + 3 * WELEMS, bo + bof, o);

        float *dst = (l == L_ - 1) ? out : x;
        resid_ln_kernel<<<M_, 256>>>(o, xin, gamma + bof, beta + bof, dst, xb);
        xin = x;
    }
}

// round 16
// speedup vs baseline: 1.0700x; 1.0122x over previous
#include <cuda_runtime.h>
#include <cuda_bf16.h>
#include <math.h>

// Problem constants
#define B_ 4
#define S_ 2048
#define E_ 1024
#define H_ 16
#define D_ 64
#define L_ 4
#define M_ 8192
#define ACT_ELEMS 8388608     // B*S*E
#define WELEMS 1048576        // E*E
#define GK E_

// ---------------------------------------------------------------------------
// Scratch (static device globals)
// ---------------------------------------------------------------------------
__device__ float g_o[ACT_ELEMS];
__device__ float g_x[ACT_ELEMS];
__device__ __nv_bfloat16 g_xb[ACT_ELEMS];      // plain bf16 activations
__device__ __nv_bfloat16 g_qb[ACT_ELEMS];      // pre-scaled by log2e/32
__device__ __nv_bfloat16 g_kb[ACT_ELEMS];      // masked rows zeroed
__device__ __nv_bfloat16 g_vb[ACT_ELEMS];
__device__ __nv_bfloat16 g_ab[ACT_ELEMS];      // attention out, plain bf16
__device__ __nv_bfloat16 g_wb[16 * WELEMS];    // all layers' Wq,Wk,Wv,Wo bf16

// ---------------------------------------------------------------------------
// PTX helpers
// ---------------------------------------------------------------------------
__device__ __forceinline__ void ldsm4(unsigned &r0, unsigned &r1, unsigned &r2,
                                      unsigned &r3, unsigned a) {
    asm volatile("ldmatrix.sync.aligned.m8n8.x4.shared.b16 {%0,%1,%2,%3}, [%4];"
                 : "=r"(r0), "=r"(r1), "=r"(r2), "=r"(r3) : "r"(a));
}
__device__ __forceinline__ void ldsm4t(unsigned &r0, unsigned &r1, unsigned &r2,
                                       unsigned &r3, unsigned a) {
    asm volatile("ldmatrix.sync.aligned.m8n8.x4.trans.shared.b16 {%0,%1,%2,%3}, [%4];"
                 : "=r"(r0), "=r"(r1), "=r"(r2), "=r"(r3) : "r"(a));
}
__device__ __forceinline__ void mma_bf16(float *c, const unsigned *a,
                                         unsigned b0, unsigned b1) {
    asm volatile(
        "mma.sync.aligned.m16n8k16.row.col.f32.bf16.bf16.f32 "
        "{%0,%1,%2,%3}, {%4,%5,%6,%7}, {%8,%9}, {%0,%1,%2,%3};"
        : "+f"(c[0]), "+f"(c[1]), "+f"(c[2]), "+f"(c[3])
        : "r"(a[0]), "r"(a[1]), "r"(a[2]), "r"(a[3]), "r"(b0), "r"(b1));
}
__device__ __forceinline__ void cpa16(unsigned s, const void *g) {
    asm volatile("cp.async.cg.shared.global [%0], [%1], 16;" :: "r"(s), "l"(g));
}
__device__ __forceinline__ void cpcommit() { asm volatile("cp.async.commit_group;"); }

__device__ __forceinline__ unsigned pack2(float a, float b) {
    unsigned r;
    asm("cvt.rn.bf16x2.f32 %0, %1, %2;" : "=r"(r) : "f"(b), "f"(a));
    return r;
}
__device__ __forceinline__ float ex2f(float x) {
    float y;
    asm("ex2.approx.f32 %0, %1;" : "=f"(y) : "f"(x));
    return y;
}

// ---------------------------------------------------------------------------
// Conversion kernels
// ---------------------------------------------------------------------------
__global__ __launch_bounds__(256) void cvt_kernel(
    const float4 *__restrict__ src, uint2 *__restrict__ dst, int n4)
{
    int i = blockIdx.x * blockDim.x + threadIdx.x;
    if (i >= n4) return;
    float4 v = src[i];
    dst[i] = make_uint2(pack2(v.x, v.y), pack2(v.z, v.w));
}

// Weight prep, ALL layers in one launch: grid.y = weight, grid.z = layer.
__global__ __launch_bounds__(256) void wprep_kernel(
    const float4 *__restrict__ s0, const float4 *__restrict__ s1,
    const float4 *__restrict__ s2, const float4 *__restrict__ s3,
    uint2 *__restrict__ wb, int n4)
{
    int i = blockIdx.x * blockDim.x + threadIdx.x;
    if (i >= n4) return;
    int y = blockIdx.y, l = blockIdx.z;
    const float4 *src = ((y == 0) ? s0 : (y == 1) ? s1 : (y == 2) ? s2 : s3)
                        + (size_t)l * (WELEMS / 4) + i;
    float4 v = *src;
    wb[((size_t)l * 4 + y) * (WELEMS / 4) + i] =
        make_uint2(pack2(v.x, v.y), pack2(v.z, v.w));
}

// ---------------------------------------------------------------------------
// Plain bf16 GEMM: C = (A[M,K] @ W[N,K]^T + bias) * scale [* rowmask]
// Block 256x128, 8 warps, warp tile 64x64 (4x2), k-chunk 64, 144B rows.
// 3-stage cp.async pipeline, ONE __syncthreads per chunk:
//   wait_group(1) -> sync (publishes chunk i AND proves compute i-1 done)
//   -> issue loads chunk i+2 (stage (i+2)%3 == (i-1)%3, safe) -> compute i.
// ---------------------------------------------------------------------------
#define ATILE 36864             // 256 rows * 144 B (A)
#define WTILE 18432             // 128 rows * 144 B (W)
#define PSTAGE (ATILE + WTILE)  // 55296
#define PGEMM_SMEM (3 * PSTAGE) // 165888

template <bool F32OUT>
__device__ __forceinline__ void pgemm_body(
    const __nv_bfloat16 *__restrict__ A, const __nv_bfloat16 *__restrict__ W,
    const float *__restrict__ bias, float scale, const int *__restrict__ kmask,
    __nv_bfloat16 *__restrict__ Cb, float *__restrict__ Cf)
{
    extern __shared__ char smc[];
    unsigned sb = (unsigned)__cvta_generic_to_shared(smc);

    const int tid = threadIdx.x;
    const int bm = blockIdx.y * 256, bn = blockIdx.x * 128;
    const int warp = tid >> 5, lane = tid & 31;
    const int wm = (warp >> 1) * 64, wn = (warp & 1) * 64;
    const int gid = lane >> 2, tig = lane & 3;
    const int lrow = lane & 15, lhalf = (lane >> 4) * 16;

    // Loaders: every thread loads its A row; threads 0-127 also load a W row.
    const __nv_bfloat16 *ga = A + (size_t)(bm + tid) * GK;
    const __nv_bfloat16 *gw = W + (size_t)(bn + (tid & 127)) * GK;
    const unsigned sdA = sb + tid * 144;
    const unsigned sdW = sb + ATILE + (tid & 127) * 144;
    const bool loadw = tid < 128;

    float acc[4][8][4];
#pragma unroll
    for (int mt = 0; mt < 4; mt++)
#pragma unroll
        for (int nt = 0; nt < 8; nt++)
#pragma unroll
            for (int e = 0; e < 4; e++) acc[mt][nt][e] = 0.0f;

    // Prologue: chunks 0,1 into stages 0,1 (one group each)
#pragma unroll
    for (int s = 0; s < 2; s++) {
        unsigned st = s * PSTAGE;
#pragma unroll
        for (int c = 0; c < 8; c++) {
            cpa16(sdA + st + c * 16, ga + s * 64 + c * 8);
            if (loadw) cpa16(sdW + st + c * 16, gw + s * 64 + c * 8);
        }
        cpcommit();
    }

    const int NK = GK / 64;           // 16
    int cst = 0, lst = 2;
    for (int ks = 0; ks < NK; ks++) {
        asm volatile("cp.async.wait_group 1;");
        __syncthreads();              // chunk ks visible; compute ks-1 done
        if (ks + 2 < NK) {
            unsigned st = lst * PSTAGE;
#pragma unroll
            for (int c = 0; c < 8; c++) {
                cpa16(sdA + st + c * 16, ga + (ks + 2) * 64 + c * 8);
                if (loadw) cpa16(sdW + st + c * 16, gw + (ks + 2) * 64 + c * 8);
            }
        }
        cpcommit();                   // empty at tail: keeps accounting uniform

        unsigned s0 = sb + cst * PSTAGE;
#pragma unroll
        for (int k16 = 0; k16 < 4; k16++) {
            unsigned af[4][4], wf[8][2];
#pragma unroll
            for (int mt = 0; mt < 4; mt++) {
                unsigned addr = s0 + (wm + mt * 16 + lrow) * 144 + k16 * 32 + lhalf;
                ldsm4(af[mt][0], af[mt][1], af[mt][2], af[mt][3], addr);
            }
#pragma unroll
            for (int pr = 0; pr < 4; pr++) {
                unsigned addr = s0 + ATILE + (wn + pr * 16 + lrow) * 144 +
                                k16 * 32 + lhalf;
                unsigned r0, r1, r2, r3;
                ldsm4(r0, r1, r2, r3, addr);
                wf[2 * pr][0] = r0; wf[2 * pr + 1][0] = r1;
                wf[2 * pr][1] = r2; wf[2 * pr + 1][1] = r3;
            }
#pragma unroll
            for (int mt = 0; mt < 4; mt++)
#pragma unroll
                for (int nt = 0; nt < 8; nt++)
                    mma_bf16(acc[mt][nt], af[mt], wf[nt][0], wf[nt][1]);
        }
        if (++cst == 3) cst = 0;
        if (++lst == 3) lst = 0;
    }

    // Per-row mask scales (K projection only): 0 for masked token rows.
    float rs[4][2];
#pragma unroll
    for (int mt = 0; mt < 4; mt++) {
        int r0 = bm + wm + mt * 16 + gid;
        if (kmask) {
            rs[mt][0] = kmask[r0] ? 0.0f : scale;
            rs[mt][1] = kmask[r0 + 8] ? 0.0f : scale;
        } else {
            rs[mt][0] = scale; rs[mt][1] = scale;
        }
    }

#pragma unroll
    for (int nt = 0; nt < 8; nt++) {
        int col = bn + wn + nt * 8 + 2 * tig;
        float2 bv2 = *(const float2 *)(bias + col);
#pragma unroll
        for (int mt = 0; mt < 4; mt++) {
            int r0 = bm + wm + mt * 16 + gid;
            float v00 = (acc[mt][nt][0] + bv2.x) * rs[mt][0];
            float v01 = (acc[mt][nt][1] + bv2.y) * rs[mt][0];
            float v10 = (acc[mt][nt][2] + bv2.x) * rs[mt][1];
            float v11 = (acc[mt][nt][3] + bv2.y) * rs[mt][1];
            if (F32OUT) {
                *(float2 *)(Cf + (size_t)r0 * E_ + col) = make_float2(v00, v01);
                *(float2 *)(Cf + (size_t)(r0 + 8) * E_ + col) = make_float2(v10, v11);
            } else {
                *(unsigned *)(Cb + (size_t)r0 * E_ + col) = pack2(v00, v01);
                *(unsigned *)(Cb + (size_t)(r0 + 8) * E_ + col) = pack2(v10, v11);
            }
        }
    }
}

// Fused QKV projection; Q pre-scaled by log2e/32, K rows zeroed by mask.
__global__ __launch_bounds__(256, 1) void gemm_qkv_plain(
    const __nv_bfloat16 *__restrict__ A, const __nv_bfloat16 *__restrict__ WB,
    const float *__restrict__ bq, const float *__restrict__ bk,
    const float *__restrict__ bv, const int *__restrict__ mask,
    __nv_bfloat16 *qb, __nv_bfloat16 *kb, __nv_bfloat16 *vb)
{
    const int z = blockIdx.z;
    const __nv_bfloat16 *W = WB + (size_t)z * WELEMS;
    const float *bias = (z == 0) ? bq : (z == 1) ? bk : bv;
    __nv_bfloat16 *C = (z == 0) ? qb : (z == 1) ? kb : vb;
    float scale = (z == 0) ? 0.04508422f : 1.0f;   // log2(e)/32
    const int *kmask = (z == 1) ? mask : nullptr;
    pgemm_body<false>(A, W, bias, scale, kmask, C, nullptr);
}

// Output projection (Wo), fp32 output for residual+LN.
__global__ __launch_bounds__(256, 1) void gemm_wo_plain(
    const __nv_bfloat16 *__restrict__ A, const __nv_bfloat16 *__restrict__ W,
    const float *__restrict__ bias, float *__restrict__ C)
{
    pgemm_body<true>(A, W, bias, 1.0f, nullptr, nullptr, C);
}

// ---------------------------------------------------------------------------
// Flash attention (8 warps x m16, 256 thr, 2 CTAs/SM). 3-stage pipeline,
// one __syncthreads per key tile (same protocol as the GEMM).
// No mask path (masked K rows are zero -> p = ex2(0) = 1 exactly).
// No online max. Q pre-scaled by log2e/32.
// ---------------------------------------------------------------------------
#define KT 9216                 // 64 rows x 144 B
#define AST (2 * KT)            // 18432 (K + V)
#define ATT_SMEM (3 * AST)      // 55296

__device__ __forceinline__ void attn_load_stage(
    unsigned sb, int st, int tid,
    const __nv_bfloat16 *K, const __nv_bfloat16 *V,
    size_t hb2, int kt)
{
    unsigned s0 = sb + st * AST;
    const int row = tid >> 2;
    const int cb = (tid & 3) * 2;
    size_t gof = hb2 + (size_t)(kt * 64 + row) * E_ + cb * 8;
    unsigned sr = s0 + row * 144 + cb * 16;
    cpa16(sr,           K + gof);
    cpa16(sr + 16,      K + gof + 8);
    cpa16(sr + KT,      V + gof);
    cpa16(sr + KT + 16, V + gof + 8);
}

__global__ __launch_bounds__(256, 2) void attn_mma_kernel(
    const __nv_bfloat16 *__restrict__ Q, const __nv_bfloat16 *__restrict__ K,
    const __nv_bfloat16 *__restrict__ V, __nv_bfloat16 *__restrict__ Ab)
{
    extern __shared__ char smc[];
    unsigned sb = (unsigned)__cvta_generic_to_shared(smc);

    const int qt = blockIdx.x, h = blockIdx.y, b = blockIdx.z;
    const int tid = threadIdx.x, warp = tid >> 5, lane = tid & 31;
    const int gid = lane >> 2, tig = lane & 3;
    const int lrow = lane & 15, lhalf = (lane >> 4) * 16;
    const size_t hb2 = (size_t)b * S_ * E_ + (size_t)h * D_;
    const int q0 = qt * 128 + warp * 16;

    unsigned qf[4][4];
    {
        const __nv_bfloat16 *r0 = Q + hb2 + (size_t)(q0 + gid) * E_;
        const __nv_bfloat16 *r1 = r0 + 8 * E_;
#pragma unroll
        for (int kc = 0; kc < 4; kc++) {
            int c0 = kc * 16 + 2 * tig;
            qf[kc][0] = *(const unsigned *)(r0 + c0);
            qf[kc][1] = *(const unsigned *)(r1 + c0);
            qf[kc][2] = *(const unsigned *)(r0 + c0 + 8);
            qf[kc][3] = *(const unsigned *)(r1 + c0 + 8);
        }
    }

    float o[8][4];
#pragma unroll
    for (int nt = 0; nt < 8; nt++)
#pragma unroll
        for (int e = 0; e < 4; e++) o[nt][e] = 0.0f;
    float lsum0 = 0.0f, lsum1 = 0.0f;

    // Prologue: tiles 0,1 into stages 0,1
    attn_load_stage(sb, 0, tid, K, V, hb2, 0);
    cpcommit();
    attn_load_stage(sb, 1, tid, K, V, hb2, 1);
    cpcommit();

    const unsigned FULL = 0xffffffffu;
    int cst = 0, lst = 2;

    for (int kt = 0; kt < 32; kt++) {
        asm volatile("cp.async.wait_group 1;");
        __syncthreads();              // tile kt visible; compute kt-1 done
        if (kt + 2 < 32)
            attn_load_stage(sb, lst, tid, K, V, hb2, kt + 2);
        cpcommit();

        unsigned s0 = sb + cst * AST;

        // S = (Q*log2e/32) K^T  == energy in log2 domain (0 for masked keys)
        float s[8][4];
#pragma unroll
        for (int nt = 0; nt < 8; nt++)
            s[nt][0] = s[nt][1] = s[nt][2] = s[nt][3] = 0.0f;

#pragma unroll
        for (int nt16 = 0; nt16 < 4; nt16++) {
#pragma unroll
            for (int kc = 0; kc < 4; kc++) {
                unsigned addr = s0 + (nt16 * 16 + lrow) * 144 + kc * 32 + lhalf;
                unsigned k0, k1, k2, k3;
                ldsm4(k0, k1, k2, k3, addr);
                mma_bf16(s[2 * nt16],     qf[kc], k0, k2);
                mma_bf16(s[2 * nt16 + 1], qf[kc], k1, k3);
            }
        }

        // p = exp2(s), accumulate denominator (masked keys give p = 1)
#pragma unroll
        for (int nt = 0; nt < 8; nt++) {
            s[nt][0] = ex2f(s[nt][0]);
            s[nt][1] = ex2f(s[nt][1]);
            s[nt][2] = ex2f(s[nt][2]);
            s[nt][3] = ex2f(s[nt][3]);
            lsum0 += s[nt][0] + s[nt][1];
            lsum1 += s[nt][2] + s[nt][3];
        }

        // O += P V  (P C-layout packs directly into PV A-fragment)
        const int vm = lane >> 3, vi = lane & 7;
#pragma unroll
        for (int kc = 0; kc < 4; kc++) {
            unsigned pb[4];
            pb[0] = pack2(s[2 * kc][0],     s[2 * kc][1]);
            pb[1] = pack2(s[2 * kc][2],     s[2 * kc][3]);
            pb[2] = pack2(s[2 * kc + 1][0], s[2 * kc + 1][1]);
            pb[3] = pack2(s[2 * kc + 1][2], s[2 * kc + 1][3]);
#pragma unroll
            for (int j = 0; j < 4; j++) {
                unsigned vaddr = s0 + KT +
                                 (kc * 16 + ((vm >> 1) & 1) * 8 + vi) * 144 +
                                 (j * 16 + (vm & 1) * 8) * 2;
                unsigned v0, v1, v2, v3;
                ldsm4t(v0, v1, v2, v3, vaddr);
                mma_bf16(o[2 * j],     pb, v0, v2);
                mma_bf16(o[2 * j + 1], pb, v1, v3);
            }
        }
        if (++cst == 3) cst = 0;
        if (++lst == 3) lst = 0;
    }

    // one quad-reduction of the denominators, then normalize + write bf16
    lsum0 += __shfl_xor_sync(FULL, lsum0, 1);
    lsum0 += __shfl_xor_sync(FULL, lsum0, 2);
    lsum1 += __shfl_xor_sync(FULL, lsum1, 1);
    lsum1 += __shfl_xor_sync(FULL, lsum1, 2);
    float i0 = 1.0f / lsum0, i1 = 1.0f / lsum1;
#pragma unroll
    for (int nt = 0; nt < 8; nt++) {
        int col = nt * 8 + 2 * tig;
        size_t ia = hb2 + (size_t)(q0 + gid) * E_ + col;
        size_t ib = hb2 + (size_t)(q0 + gid + 8) * E_ + col;
        *(unsigned *)(Ab + ia) = pack2(o[nt][0] * i0, o[nt][1] * i0);
        *(unsigned *)(Ab + ib) = pack2(o[nt][2] * i1, o[nt][3] * i1);
    }
}

// ---------------------------------------------------------------------------
// Residual add + LayerNorm; emits fp32 out + plain bf16 for next QKV input.
// ---------------------------------------------------------------------------
__global__ __launch_bounds__(256) void resid_ln_kernel(
    const float *__restrict__ o, const float *__restrict__ x,
    const float *__restrict__ gamma, const float *__restrict__ beta,
    float *__restrict__ out, __nv_bfloat16 *__restrict__ ob)
{
    const int row = blockIdx.x;
    const int tid = threadIdx.x;
    const float *orow = o + (size_t)row * E_;
    const float *xrow = x + (size_t)row * E_;

    float y[4];
    float s = 0.0f, s2 = 0.0f;
#pragma unroll
    for (int t = 0; t < 4; t++) {
        int c = tid + t * 256;
        y[t] = orow[c] + xrow[c];
        s += y[t];
        s2 += y[t] * y[t];
    }

    __shared__ float red[16];
#pragma unroll
    for (int off = 16; off > 0; off >>= 1) {
        s += __shfl_xor_sync(0xffffffffu, s, off);
        s2 += __shfl_xor_sync(0xffffffffu, s2, off);
    }
    const int warp = tid >> 5, lane = tid & 31;
    if (lane == 0) { red[warp] = s; red[8 + warp] = s2; }
    __syncthreads();

    float ts = 0.0f, ts2 = 0.0f;
#pragma unroll
    for (int w = 0; w < 8; w++) { ts += red[w]; ts2 += red[8 + w]; }

    const float mu = ts * (1.0f / E_);
    const float var = ts2 * (1.0f / E_) - mu * mu;
    const float inv = rsqrtf(var + 1e-5f);

    float *outrow = out + (size_t)row * E_;
#pragma unroll
    for (int t = 0; t < 4; t++) {
        int c = tid + t * 256;
        float val = (y[t] - mu) * inv * gamma[c] + beta[c];
        outrow[c] = val;
        ob[(size_t)row * E_ + c] = __float2bfloat16(val);
    }
}

// ---------------------------------------------------------------------------
// Launch
// ---------------------------------------------------------------------------
extern "C" void kernel_launch(void *const *d_in, const int *in_sizes, int n_in,
                              void *d_out, int out_size)
{
    (void)in_sizes; (void)n_in; (void)out_size;

    const float *value = (const float *)d_in[0];
    const int *mask = (const int *)d_in[1];
    const float *Wq = (const float *)d_in[2];  const float *bq = (const float *)d_in[3];
    const float *Wk = (const float *)d_in[4];  const float *bk = (const float *)d_in[5];
    const float *Wv = (const float *)d_in[6];  const float *bv = (const float *)d_in[7];
    const float *Wo = (const float *)d_in[8];  const float *bo = (const float *)d_in[9];
    const float *gamma = (const float *)d_in[10];
    const float *beta = (const float *)d_in[11];
    float *out = (float *)d_out;

    float *o, *x;
    __nv_bfloat16 *xb, *qb, *kb, *vb, *ab, *wb;
    cudaGetSymbolAddress((void **)&o, g_o);
    cudaGetSymbolAddress((void **)&x, g_x);
    cudaGetSymbolAddress((void **)&xb, g_xb);
    cudaGetSymbolAddress((void **)&qb, g_qb);
    cudaGetSymbolAddress((void **)&kb, g_kb);
    cudaGetSymbolAddress((void **)&vb, g_vb);
    cudaGetSymbolAddress((void **)&ab, g_ab);
    cudaGetSymbolAddress((void **)&wb, g_wb);

    cudaFuncSetAttribute(gemm_qkv_plain,
                         cudaFuncAttributeMaxDynamicSharedMemorySize, PGEMM_SMEM);
    cudaFuncSetAttribute(gemm_wo_plain,
                         cudaFuncAttributeMaxDynamicSharedMemorySize, PGEMM_SMEM);
    cudaFuncSetAttribute(attn_mma_kernel,
                         cudaFuncAttributeMaxDynamicSharedMemorySize, ATT_SMEM);

    dim3 qkvgrid(E_ / 128, M_ / 256, 3);   // (8, 32, 3)
    dim3 ogrid(E_ / 128, M_ / 256, 1);     // (8, 32)
    dim3 agrid(S_ / 128, H_, B_);
    dim3 wgrid(WELEMS / 4 / 256, 4, L_);
    const int n4a = ACT_ELEMS / 4;

    cvt_kernel<<<(n4a + 255) / 256, 256>>>((const float4 *)value,
                                           (uint2 *)xb, n4a);
    // All layers' weights converted once, up front.
    wprep_kernel<<<wgrid, 256>>>(
        (const float4 *)Wq, (const float4 *)Wk,
        (const float4 *)Wv, (const float4 *)Wo,
        (uint2 *)wb, WELEMS / 4);

    const float *xin = value;
    for (int l = 0; l < L_; l++) {
        size_t bof = (size_t)l * E_;
        __nv_bfloat16 *wl = wb + (size_t)l * 4 * WELEMS;

        gemm_qkv_plain<<<qkvgrid, 256, PGEMM_SMEM>>>(
            xb, wl, bq + bof, bk + bof, bv + bof, mask, qb, kb, vb);

        attn_mma_kernel<<<agrid, 256, ATT_SMEM>>>(qb, kb, vb, ab);

        gemm_wo_plain<<<ogrid, 256, PGEMM_SMEM>>>(
            ab, wl + 3 * WELEMS, bo + bof, o);

        float *dst = (l == L_ - 1) ? out : x;
        resid_ln_kernel<<<M_, 256>>>(o, xin, gamma + bof, beta + bof, dst, xb);
        xin = x;
    }
}